// round 6
// baseline (speedup 1.0000x reference)
#include <cuda_runtime.h>
#include <cuda_fp16.h>
#include <cstdint>

// ============================ config ============================
#define K_DIM 1024
#define N_DIM 1024
#define BM 128
#define BN 128
#define BK 64
#define KTILES (K_DIM / BK)   // 16
#define NSTAGE 3
#define THREADS 128
#define NTILES_N (N_DIM / BN) // 8

#define A_STAGE (BM * BK * 2)                 // 16384 B
#define B_STAGE (BN * BK * 2)                 // 16384 B
#define SMEM_TILES 1024
#define SMEM_TOTAL (SMEM_TILES + NSTAGE * (A_STAGE + B_STAGE))  // 99328 B

#define NC_BLOCKS 32768   // convert blocks in prepass (65536*1024/8/256)

// static scratch (allocation-free rule: __device__ globals)
__device__ __half g_xh[(size_t)65536 * K_DIM];   // x converted to fp16
__device__ __half g_Wt[(size_t)N_DIM * K_DIM];   // W transposed to (N,K) fp16

// ============================ helpers ============================
__device__ __forceinline__ uint32_t smem_u32(const void* p) {
    uint32_t a;
    asm("{ .reg .u64 t; cvta.to.shared.u64 t, %1; cvt.u32.u64 %0, t; }"
        : "=r"(a) : "l"(p));
    return a;
}

__device__ __forceinline__ void cp_async16(uint32_t dst, const void* src) {
    asm volatile("cp.async.cg.shared.global [%0], [%1], 16;" :: "r"(dst), "l"(src));
}
#define CP_COMMIT() asm volatile("cp.async.commit_group;" ::: "memory")
#define CP_WAIT(n)  asm volatile("cp.async.wait_group %0;" :: "n"(n) : "memory")

__device__ __forceinline__ void ldsm_x4(uint32_t& r0, uint32_t& r1,
                                        uint32_t& r2, uint32_t& r3, uint32_t addr) {
    asm volatile("ldmatrix.sync.aligned.m8n8.x4.shared.b16 {%0,%1,%2,%3}, [%4];"
                 : "=r"(r0), "=r"(r1), "=r"(r2), "=r"(r3) : "r"(addr));
}

__device__ __forceinline__ void mma16816(float* d, const uint32_t* a,
                                         uint32_t b0, uint32_t b1) {
    asm volatile(
        "mma.sync.aligned.m16n8k16.row.col.f32.f16.f16.f32 "
        "{%0,%1,%2,%3}, {%4,%5,%6,%7}, {%8,%9}, {%0,%1,%2,%3};"
        : "+f"(d[0]), "+f"(d[1]), "+f"(d[2]), "+f"(d[3])
        : "r"(a[0]), "r"(a[1]), "r"(a[2]), "r"(a[3]), "r"(b0), "r"(b1));
}

// sigmoid via single-MUFU tanh.approx: sig(v) = 0.5*tanh(0.5v) + 0.5
__device__ __forceinline__ float fsig(float v) {
    float t;
    asm("tanh.approx.f32 %0, %1;" : "=f"(t) : "f"(v * 0.5f));
    return fmaf(0.5f, t, 0.5f);
}

// ============================ merged pre-pass ============================
__global__ void prepass_kernel(const float* __restrict__ x,
                               const float* __restrict__ W) {
    if (blockIdx.x < NC_BLOCKS) {
        size_t i = ((size_t)blockIdx.x * 256 + threadIdx.x) * 8;
        float4 f0 = *reinterpret_cast<const float4*>(x + i);
        float4 f1 = *reinterpret_cast<const float4*>(x + i + 4);
        __half2 h0 = __floats2half2_rn(f0.x, f0.y);
        __half2 h1 = __floats2half2_rn(f0.z, f0.w);
        __half2 h2 = __floats2half2_rn(f1.x, f1.y);
        __half2 h3 = __floats2half2_rn(f1.z, f1.w);
        uint4 o;
        o.x = *reinterpret_cast<uint32_t*>(&h0);
        o.y = *reinterpret_cast<uint32_t*>(&h1);
        o.z = *reinterpret_cast<uint32_t*>(&h2);
        o.w = *reinterpret_cast<uint32_t*>(&h3);
        *reinterpret_cast<uint4*>(&g_xh[i]) = o;
    } else {
        __shared__ float t[32][33];
        int bidx = blockIdx.x - NC_BLOCKS;
        int bx = bidx & 31;        // n tile
        int by = bidx >> 5;        // k tile
        int tx = threadIdx.x & 31;
        int ty = threadIdx.x >> 5; // 0..7
        int n = bx * 32 + tx;
        int k = by * 32 + ty;
#pragma unroll
        for (int i = 0; i < 4; ++i)
            t[ty + i * 8][tx] = W[(size_t)(k + i * 8) * N_DIM + n];
        __syncthreads();
        int n2 = bx * 32 + ty;
        int k2 = by * 32 + tx;
#pragma unroll
        for (int i = 0; i < 4; ++i)
            g_Wt[(size_t)(n2 + i * 8) * K_DIM + k2] =
                __float2half(t[tx][ty + i * 8]);
    }
}

// ============================ pipeline loads ============================
__device__ __forceinline__ void load_stage(uint32_t dstA, uint32_t dstB,
                                           const __half* __restrict__ ag,
                                           const __half* __restrict__ bg, int tid) {
#pragma unroll
    for (int i = 0; i < 8; ++i) {
        int id = i * THREADS + tid;
        int r = id >> 3, c = id & 7;
        cp_async16(dstA + r * 128 + (((c ^ (r & 7))) << 4), ag + (size_t)r * K_DIM + c * 8);
    }
#pragma unroll
    for (int i = 0; i < 8; ++i) {
        int id = i * THREADS + tid;
        int r = id >> 3, c = id & 7;
        cp_async16(dstB + r * 128 + (((c ^ (r & 7))) << 4), bg + (size_t)r * K_DIM + c * 8);
    }
}

// ============================ main fused persistent kernel ============================
// 2*numSMs CTAs; each loops over tiles (stride grid). cp.async stage cursor is
// GLOBAL across tiles: the pipeline never drains at tile boundaries, so the
// epilogue overlaps the next tile's loads and the prologue cost is paid once.
__global__ __launch_bounds__(THREADS, 2)
void fused_gemm_gn_swish_kernel(const float* __restrict__ bias,
                                const float* __restrict__ mw,
                                float* __restrict__ out,
                                int nTiles) {
    extern __shared__ char smem[];
    uint32_t sb = smem_u32(smem);
    const int tid  = threadIdx.x;
    const int lane = tid & 31;
    const int wid  = tid >> 5;
    const int wm   = wid >> 1;   // 0..1  M warp row (64 rows)
    const int wn   = wid & 1;    // 0..1  N warp col (64 cols)
    const int grid = gridDim.x;

    uint32_t sA = sb + SMEM_TILES;
    uint32_t sB = sA + NSTAGE * A_STAGE;

    // ldmatrix lane addressing
    const int lrow   = lane & 15;
    const int lchunk = lane >> 4;
    const uint32_t aRow = (uint32_t)(wm * 64 + lrow) * 128;
    const uint32_t bRow = (uint32_t)(wn * 64 + lrow) * 128;
    uint32_t soff[4];
#pragma unroll
    for (int ks = 0; ks < 4; ++ks)
        soff[ks] = (uint32_t)(((ks * 2 + lchunk) ^ (lrow & 7)) << 4);

    int t = blockIdx.x;

    // global load cursor (tile lt, ktile lkt, smem buffer lbuf)
    int lt = t, lkt = 0, lbuf = 0;

    // prologue: fill 2 stages
#pragma unroll
    for (int s = 0; s < 2; ++s) {
        const __half* ag = g_xh + (size_t)((lt >> 3) * BM) * K_DIM + lkt * BK;
        const __half* bg = g_Wt + (size_t)((lt & 7) * BN) * K_DIM + lkt * BK;
        load_stage(sA + lbuf * A_STAGE, sB + lbuf * B_STAGE, ag, bg, tid);
        CP_COMMIT();
        if (++lbuf == NSTAGE) lbuf = 0;
        if (++lkt == KTILES) { lkt = 0; lt += grid; }
    }
    int rbuf = 0;

    float acc[4][8][4];
#pragma unroll
    for (int i = 0; i < 4; ++i)
#pragma unroll
        for (int j = 0; j < 8; ++j)
#pragma unroll
            for (int e = 0; e < 4; ++e) acc[i][j][e] = 0.0f;

    while (t < nTiles) {
        const bool lastTile = (t + grid >= nTiles);

        for (int kt = 0; kt < KTILES; ++kt) {
            if (lastTile && kt == KTILES - 1) { CP_WAIT(0); } else { CP_WAIT(1); }
            __syncthreads();

            // issue the next global stage (may belong to the NEXT tile)
            if (lt < nTiles) {
                const __half* ag = g_xh + (size_t)((lt >> 3) * BM) * K_DIM + lkt * BK;
                const __half* bg = g_Wt + (size_t)((lt & 7) * BN) * K_DIM + lkt * BK;
                load_stage(sA + lbuf * A_STAGE, sB + lbuf * B_STAGE, ag, bg, tid);
                CP_COMMIT();
                if (++lbuf == NSTAGE) lbuf = 0;
                if (++lkt == KTILES) { lkt = 0; lt += grid; }
            }

            uint32_t aB = sA + rbuf * A_STAGE + aRow;
            uint32_t bB = sB + rbuf * B_STAGE + bRow;
#pragma unroll
            for (int ks = 0; ks < 4; ++ks) {
                uint32_t a[4][4], b[4][4];
#pragma unroll
                for (int mi = 0; mi < 4; ++mi)
                    ldsm_x4(a[mi][0], a[mi][1], a[mi][2], a[mi][3],
                            aB + mi * (16 * 128) + soff[ks]);
#pragma unroll
                for (int p = 0; p < 4; ++p)
                    ldsm_x4(b[p][0], b[p][1], b[p][2], b[p][3],
                            bB + p * (16 * 128) + soff[ks]);
#pragma unroll
                for (int mi = 0; mi < 4; ++mi) {
#pragma unroll
                    for (int ni = 0; ni < 8; ++ni) {
                        uint32_t b0 = (ni & 1) ? b[ni >> 1][1] : b[ni >> 1][0];
                        uint32_t b1 = (ni & 1) ? b[ni >> 1][3] : b[ni >> 1][2];
                        mma16816(acc[mi][ni], a[mi], b0, b1);
                    }
                }
            }
            if (++rbuf == NSTAGE) rbuf = 0;
        }

        // -------- epilogue (overlaps next tile's in-flight cp.async loads) --------
        {
            const int m0 = (t >> 3) * BM;
            const int n0 = (t & 7) * BN;
            const int q  = lane >> 2;
            const int qt = lane & 3;
            const float inv32 = 1.0f / 32.0f;
            const float* bp = bias + n0 + wn * 64 + qt * 2;
            const float* wp = mw   + n0 + wn * 64 + qt * 2;

#pragma unroll
            for (int mi = 0; mi < 4; ++mi) {
#pragma unroll
                for (int half = 0; half < 2; ++half) {
                    int row = m0 + wm * 64 + mi * 16 + half * 8 + q;
                    float* op = out + (size_t)row * N_DIM + n0 + wn * 64;
#pragma unroll
                    for (int g2 = 0; g2 < 2; ++g2) {
                        float v[8];
                        float sum = 0.0f, ssq = 0.0f;
#pragma unroll
                        for (int nj = 0; nj < 4; ++nj) {
                            int ni = g2 * 4 + nj;
                            float2 bv = *reinterpret_cast<const float2*>(bp + ni * 8);
#pragma unroll
                            for (int e = 0; e < 2; ++e) {
                                float val = acc[mi][ni][half * 2 + e] + ((e == 0) ? bv.x : bv.y);
                                acc[mi][ni][half * 2 + e] = 0.0f;   // fused re-zero
                                v[nj * 2 + e] = val;
                                sum += val;
                                ssq = fmaf(val, val, ssq);
                            }
                        }
                        sum += __shfl_xor_sync(0xffffffffu, sum, 1);
                        ssq += __shfl_xor_sync(0xffffffffu, ssq, 1);
                        sum += __shfl_xor_sync(0xffffffffu, sum, 2);
                        ssq += __shfl_xor_sync(0xffffffffu, ssq, 2);
                        float mean = sum * inv32;
                        float var  = fmaf(ssq, inv32, -mean * mean);
                        float rstd = rsqrtf(var + 1e-5f);

#pragma unroll
                        for (int nj = 0; nj < 4; ++nj) {
                            int ni = g2 * 4 + nj;
                            float2 wv = *reinterpret_cast<const float2*>(wp + ni * 8);
                            float2 o;
#pragma unroll
                            for (int e = 0; e < 2; ++e) {
                                float nv = (v[nj * 2 + e] - mean) * rstd;
                                float s  = nv * fsig(nv);
                                float mm = s * ((e == 0) ? wv.x : wv.y);
                                float ov = mm * fsig(mm);
                                if (e == 0) o.x = ov; else o.y = ov;
                            }
                            __stcs(reinterpret_cast<float2*>(op + ni * 8 + qt * 2), o);
                        }
                    }
                }
            }
        }

        t += grid;
    }
}

// ============================ launch ============================
extern "C" void kernel_launch(void* const* d_in, const int* in_sizes, int n_in,
                              void* d_out, int out_size) {
    const float* x  = (const float*)d_in[0];
    const float* W  = (const float*)d_in[1];
    const float* b  = (const float*)d_in[2];
    const float* mw = (const float*)d_in[3];
    float* out = (float*)d_out;

    const size_t M = (size_t)in_sizes[0] / K_DIM;   // 65536
    const int nTiles = (int)(M / BM) * NTILES_N;    // 4096

    // 1) merged pre-pass: x -> fp16 and W -> Wt fp16
    prepass_kernel<<<NC_BLOCKS + (N_DIM / 32) * (K_DIM / 32), 256>>>(x, W);

    // 2) persistent fused GEMM + bias + GroupNorm + Swish chain
    int numSMs = 148;
    cudaDeviceGetAttribute(&numSMs, cudaDevAttrMultiProcessorCount, 0);
    cudaFuncSetAttribute(fused_gemm_gn_swish_kernel,
                         cudaFuncAttributeMaxDynamicSharedMemorySize, SMEM_TOTAL);
    fused_gemm_gn_swish_kernel<<<2 * numSMs, THREADS, SMEM_TOTAL>>>(b, mw, out, nTiles);
}

// round 7
// speedup vs baseline: 1.0603x; 1.0603x over previous
#include <cuda_runtime.h>
#include <cuda_fp16.h>
#include <cstdint>

// ============================ config ============================
#define K_DIM 1024
#define N_DIM 1024
#define BM 128
#define BN 128
#define BK 64
#define KTILES (K_DIM / BK)   // 16
#define NSTAGE 3
#define THREADS 128

#define A_STAGE (BM * BK * 2)                 // 16384 B
#define B_STAGE (BN * BK * 2)                 // 16384 B
#define SMEM_TOTAL (NSTAGE * (A_STAGE + B_STAGE))  // 98304 B

#define NC_BLOCKS 32768   // convert blocks in prepass (65536*1024/8/256)

// static scratch (allocation-free rule: __device__ globals)
__device__ __half g_xh[(size_t)65536 * K_DIM];   // x converted to fp16
__device__ __half g_Wt[(size_t)N_DIM * K_DIM];   // W transposed to (N,K) fp16

// ============================ helpers ============================
__device__ __forceinline__ uint32_t smem_u32(const void* p) {
    uint32_t a;
    asm("{ .reg .u64 t; cvta.to.shared.u64 t, %1; cvt.u32.u64 %0, t; }"
        : "=r"(a) : "l"(p));
    return a;
}

__device__ __forceinline__ void cp_async16(uint32_t dst, const void* src) {
    asm volatile("cp.async.cg.shared.global [%0], [%1], 16;" :: "r"(dst), "l"(src));
}
#define CP_COMMIT() asm volatile("cp.async.commit_group;" ::: "memory")
#define CP_WAIT(n)  asm volatile("cp.async.wait_group %0;" :: "n"(n) : "memory")

__device__ __forceinline__ void ldsm_x4(uint32_t& r0, uint32_t& r1,
                                        uint32_t& r2, uint32_t& r3, uint32_t addr) {
    asm volatile("ldmatrix.sync.aligned.m8n8.x4.shared.b16 {%0,%1,%2,%3}, [%4];"
                 : "=r"(r0), "=r"(r1), "=r"(r2), "=r"(r3) : "r"(addr));
}

__device__ __forceinline__ void mma16816(float* d, const uint32_t* a,
                                         uint32_t b0, uint32_t b1) {
    asm volatile(
        "mma.sync.aligned.m16n8k16.row.col.f32.f16.f16.f32 "
        "{%0,%1,%2,%3}, {%4,%5,%6,%7}, {%8,%9}, {%0,%1,%2,%3};"
        : "+f"(d[0]), "+f"(d[1]), "+f"(d[2]), "+f"(d[3])
        : "r"(a[0]), "r"(a[1]), "r"(a[2]), "r"(a[3]), "r"(b0), "r"(b1));
}

// sigmoid via single-MUFU tanh.approx: sig(v) = 0.5*tanh(0.5v) + 0.5
__device__ __forceinline__ float fsig(float v) {
    float t;
    asm("tanh.approx.f32 %0, %1;" : "=f"(t) : "f"(v * 0.5f));
    return fmaf(0.5f, t, 0.5f);
}

// ============================ merged pre-pass ============================
__global__ void prepass_kernel(const float* __restrict__ x,
                               const float* __restrict__ W) {
    if (blockIdx.x < NC_BLOCKS) {
        size_t i = ((size_t)blockIdx.x * 256 + threadIdx.x) * 8;
        float4 f0 = *reinterpret_cast<const float4*>(x + i);
        float4 f1 = *reinterpret_cast<const float4*>(x + i + 4);
        __half2 h0 = __floats2half2_rn(f0.x, f0.y);
        __half2 h1 = __floats2half2_rn(f0.z, f0.w);
        __half2 h2 = __floats2half2_rn(f1.x, f1.y);
        __half2 h3 = __floats2half2_rn(f1.z, f1.w);
        uint4 o;
        o.x = *reinterpret_cast<uint32_t*>(&h0);
        o.y = *reinterpret_cast<uint32_t*>(&h1);
        o.z = *reinterpret_cast<uint32_t*>(&h2);
        o.w = *reinterpret_cast<uint32_t*>(&h3);
        *reinterpret_cast<uint4*>(&g_xh[i]) = o;
    } else {
        __shared__ float t[32][33];
        int bidx = blockIdx.x - NC_BLOCKS;
        int bx = bidx & 31;        // n tile
        int by = bidx >> 5;        // k tile
        int tx = threadIdx.x & 31;
        int ty = threadIdx.x >> 5; // 0..7
        int n = bx * 32 + tx;
        int k = by * 32 + ty;
#pragma unroll
        for (int i = 0; i < 4; ++i)
            t[ty + i * 8][tx] = W[(size_t)(k + i * 8) * N_DIM + n];
        __syncthreads();
        int n2 = bx * 32 + ty;
        int k2 = by * 32 + tx;
#pragma unroll
        for (int i = 0; i < 4; ++i)
            g_Wt[(size_t)(n2 + i * 8) * K_DIM + k2] =
                __float2half(t[tx][ty + i * 8]);
    }
}

// ============================ main fused kernel ============================
// 4 warps in 2x2; each warp computes a 64x64 tile (acc[4][8][4], 128 regs).
// cp.async addressing fully precomputed: per ktile only base+offset adds.
__global__ __launch_bounds__(THREADS, 2)
void fused_gemm_gn_swish_kernel(const float* __restrict__ bias,
                                const float* __restrict__ mw,
                                float* __restrict__ out) {
    extern __shared__ char smem[];
    uint32_t sb = smem_u32(smem);
    const int tid  = threadIdx.x;
    const int lane = tid & 31;
    const int wid  = tid >> 5;
    const int wm   = wid >> 1;   // 0..1  (M warp row, 64 rows each)
    const int wn   = wid & 1;    // 0..1  (N warp col, 64 cols = two GN groups)
    const int m0   = blockIdx.y * BM;
    const int n0   = blockIdx.x * BN;

    uint32_t sA = sb;
    uint32_t sB = sA + NSTAGE * A_STAGE;

    // ---- precomputed cp.async offsets (A and B stage layouts identical) ----
    uint32_t goff[8];   // global element offsets (per thread)
    uint32_t smoff[8];  // swizzled smem byte offsets within a stage
#pragma unroll
    for (int i = 0; i < 8; ++i) {
        int id = i * THREADS + tid;
        int r = id >> 3, c = id & 7;
        smoff[i] = (uint32_t)(r * 128 + (((c ^ (r & 7))) << 4));
        goff[i]  = (uint32_t)(r * K_DIM + c * 8);
    }

    // running global pointers (advance by BK per stage)
    const __half* ag = g_xh + (size_t)m0 * K_DIM;
    const __half* bg = g_Wt + (size_t)n0 * K_DIM;

    // prefetch 2 stages
#pragma unroll
    for (int s = 0; s < 2; ++s) {
        uint32_t dA = sA + s * A_STAGE, dB = sB + s * B_STAGE;
#pragma unroll
        for (int i = 0; i < 8; ++i) cp_async16(dA + smoff[i], ag + goff[i]);
#pragma unroll
        for (int i = 0; i < 8; ++i) cp_async16(dB + smoff[i], bg + goff[i]);
        CP_COMMIT();
        ag += BK; bg += BK;
    }

    float acc[4][8][4];
#pragma unroll
    for (int i = 0; i < 4; ++i)
#pragma unroll
        for (int j = 0; j < 8; ++j)
#pragma unroll
            for (int e = 0; e < 4; ++e) acc[i][j][e] = 0.0f;

    // ldmatrix lane addressing (swizzle offset is row-group independent:
    // r&7 == lrow&7 because all row offsets are multiples of 16)
    const int lrow   = lane & 15;
    const int lchunk = lane >> 4;
    const uint32_t aRow = (uint32_t)(wm * 64 + lrow) * 128;
    const uint32_t bRow = (uint32_t)(wn * 64 + lrow) * 128;
    uint32_t soff[4];
#pragma unroll
    for (int ks = 0; ks < 4; ++ks)
        soff[ks] = (uint32_t)(((ks * 2 + lchunk) ^ (lrow & 7)) << 4);

    int buf = 0, ibuf = 2;
    for (int kt = 0; kt < KTILES; ++kt) {
        if (kt < KTILES - 1) { CP_WAIT(1); } else { CP_WAIT(0); }
        __syncthreads();

        // issue stage kt+2 (overwrites buffer of stage kt-1, protected by the sync)
        if (kt + 2 < KTILES) {
            uint32_t dA = sA + ibuf * A_STAGE, dB = sB + ibuf * B_STAGE;
#pragma unroll
            for (int i = 0; i < 8; ++i) cp_async16(dA + smoff[i], ag + goff[i]);
#pragma unroll
            for (int i = 0; i < 8; ++i) cp_async16(dB + smoff[i], bg + goff[i]);
            CP_COMMIT();
            ag += BK; bg += BK;
            if (++ibuf == NSTAGE) ibuf = 0;
        }

        uint32_t aB = sA + buf * A_STAGE + aRow;
        uint32_t bB = sB + buf * B_STAGE + bRow;
#pragma unroll
        for (int ks = 0; ks < 4; ++ks) {
            uint32_t a[4][4], b[4][4];
#pragma unroll
            for (int mi = 0; mi < 4; ++mi)
                ldsm_x4(a[mi][0], a[mi][1], a[mi][2], a[mi][3],
                        aB + mi * (16 * 128) + soff[ks]);
#pragma unroll
            for (int p = 0; p < 4; ++p)
                ldsm_x4(b[p][0], b[p][1], b[p][2], b[p][3],
                        bB + p * (16 * 128) + soff[ks]);
#pragma unroll
            for (int mi = 0; mi < 4; ++mi) {
#pragma unroll
                for (int ni = 0; ni < 8; ++ni) {
                    uint32_t b0 = (ni & 1) ? b[ni >> 1][1] : b[ni >> 1][0];
                    uint32_t b1 = (ni & 1) ? b[ni >> 1][3] : b[ni >> 1][2];
                    mma16816(acc[mi][ni], a[mi], b0, b1);
                }
            }
        }
        if (++buf == NSTAGE) buf = 0;
    }

    // -------- fused epilogue: bias + GroupNorm(32ch) + swish * w * swish --------
    const int q  = lane >> 2;
    const int qt = lane & 3;
    const float inv32 = 1.0f / 32.0f;
    const float* bp = bias + n0 + wn * 64 + qt * 2;
    const float* wp = mw   + n0 + wn * 64 + qt * 2;

#pragma unroll
    for (int mi = 0; mi < 4; ++mi) {
#pragma unroll
        for (int half = 0; half < 2; ++half) {
            int row = m0 + wm * 64 + mi * 16 + half * 8 + q;
            float* op = out + (size_t)row * N_DIM + n0 + wn * 64;
#pragma unroll
            for (int g2 = 0; g2 < 2; ++g2) {
                float v[8];
                float sum = 0.0f, ssq = 0.0f;
#pragma unroll
                for (int nj = 0; nj < 4; ++nj) {
                    int ni = g2 * 4 + nj;
                    float2 bv = *reinterpret_cast<const float2*>(bp + ni * 8);
#pragma unroll
                    for (int e = 0; e < 2; ++e) {
                        float val = acc[mi][ni][half * 2 + e] + ((e == 0) ? bv.x : bv.y);
                        v[nj * 2 + e] = val;
                        sum += val;
                        ssq = fmaf(val, val, ssq);
                    }
                }
                sum += __shfl_xor_sync(0xffffffffu, sum, 1);
                ssq += __shfl_xor_sync(0xffffffffu, ssq, 1);
                sum += __shfl_xor_sync(0xffffffffu, sum, 2);
                ssq += __shfl_xor_sync(0xffffffffu, ssq, 2);
                float mean = sum * inv32;
                float var  = fmaf(ssq, inv32, -mean * mean);
                float rstd = rsqrtf(var + 1e-5f);

#pragma unroll
                for (int nj = 0; nj < 4; ++nj) {
                    int ni = g2 * 4 + nj;
                    float2 wv = *reinterpret_cast<const float2*>(wp + ni * 8);
                    float2 o;
#pragma unroll
                    for (int e = 0; e < 2; ++e) {
                        float nv = (v[nj * 2 + e] - mean) * rstd;
                        float s  = nv * fsig(nv);
                        float mm = s * ((e == 0) ? wv.x : wv.y);
                        float ov = mm * fsig(mm);
                        if (e == 0) o.x = ov; else o.y = ov;
                    }
                    __stcs(reinterpret_cast<float2*>(op + ni * 8 + qt * 2), o);
                }
            }
        }
    }
}

// ============================ launch ============================
extern "C" void kernel_launch(void* const* d_in, const int* in_sizes, int n_in,
                              void* d_out, int out_size) {
    const float* x  = (const float*)d_in[0];
    const float* W  = (const float*)d_in[1];
    const float* b  = (const float*)d_in[2];
    const float* mw = (const float*)d_in[3];
    float* out = (float*)d_out;

    const size_t M = (size_t)in_sizes[0] / K_DIM;   // 65536

    // 1) merged pre-pass: x -> fp16 and W -> Wt fp16
    prepass_kernel<<<NC_BLOCKS + (N_DIM / 32) * (K_DIM / 32), 256>>>(x, W);

    // 2) fused GEMM + bias + GroupNorm + Swish chain
    cudaFuncSetAttribute(fused_gemm_gn_swish_kernel,
                         cudaFuncAttributeMaxDynamicSharedMemorySize, SMEM_TOTAL);
    dim3 grid(N_DIM / BN, (unsigned)(M / BM));  // x fastest: N-tiles of one M share A in L2
    fused_gemm_gn_swish_kernel<<<grid, THREADS, SMEM_TOTAL>>>(b, mw, out);
}

// round 8
// speedup vs baseline: 1.1113x; 1.0481x over previous
#include <cuda_runtime.h>
#include <cuda_fp16.h>
#include <cstdint>

// ============================ config ============================
#define K_DIM 1024
#define N_DIM 1024
#define BM 128
#define BN 64
#define BK 64
#define KTILES (K_DIM / BK)   // 16
#define THREADS 128

#define A_STAGE (BM * BK * 2)                 // 16384 B
#define B_STAGE (BN * BK * 2)                 // 8192 B
#define SMEM_TOTAL (2 * (A_STAGE + B_STAGE))  // 49152 B (2-stage)

#define NC_BLOCKS 32768   // convert blocks in prepass (65536*1024/8/256)

// static scratch (allocation-free rule: __device__ globals)
__device__ __half g_xh[(size_t)65536 * K_DIM];   // x converted to fp16
__device__ __half g_Wt[(size_t)N_DIM * K_DIM];   // W transposed to (N,K) fp16

// ============================ helpers ============================
__device__ __forceinline__ uint32_t smem_u32(const void* p) {
    uint32_t a;
    asm("{ .reg .u64 t; cvta.to.shared.u64 t, %1; cvt.u32.u64 %0, t; }"
        : "=r"(a) : "l"(p));
    return a;
}

__device__ __forceinline__ void cp_async16(uint32_t dst, const void* src) {
    asm volatile("cp.async.cg.shared.global [%0], [%1], 16;" :: "r"(dst), "l"(src));
}
#define CP_COMMIT() asm volatile("cp.async.commit_group;" ::: "memory")
#define CP_WAIT(n)  asm volatile("cp.async.wait_group %0;" :: "n"(n) : "memory")

__device__ __forceinline__ void ldsm_x4(uint32_t& r0, uint32_t& r1,
                                        uint32_t& r2, uint32_t& r3, uint32_t addr) {
    asm volatile("ldmatrix.sync.aligned.m8n8.x4.shared.b16 {%0,%1,%2,%3}, [%4];"
                 : "=r"(r0), "=r"(r1), "=r"(r2), "=r"(r3) : "r"(addr));
}

__device__ __forceinline__ void mma16816(float* d, const uint32_t* a,
                                         uint32_t b0, uint32_t b1) {
    asm volatile(
        "mma.sync.aligned.m16n8k16.row.col.f32.f16.f16.f32 "
        "{%0,%1,%2,%3}, {%4,%5,%6,%7}, {%8,%9}, {%0,%1,%2,%3};"
        : "+f"(d[0]), "+f"(d[1]), "+f"(d[2]), "+f"(d[3])
        : "r"(a[0]), "r"(a[1]), "r"(a[2]), "r"(a[3]), "r"(b0), "r"(b1));
}

// sigmoid via single-MUFU tanh.approx: sig(v) = 0.5*tanh(0.5v) + 0.5
__device__ __forceinline__ float fsig(float v) {
    float t;
    asm("tanh.approx.f32 %0, %1;" : "=f"(t) : "f"(v * 0.5f));
    return fmaf(0.5f, t, 0.5f);
}

// ============================ merged pre-pass ============================
__global__ void prepass_kernel(const float* __restrict__ x,
                               const float* __restrict__ W) {
    if (blockIdx.x < NC_BLOCKS) {
        size_t i = ((size_t)blockIdx.x * 256 + threadIdx.x) * 8;
        float4 f0 = *reinterpret_cast<const float4*>(x + i);
        float4 f1 = *reinterpret_cast<const float4*>(x + i + 4);
        __half2 h0 = __floats2half2_rn(f0.x, f0.y);
        __half2 h1 = __floats2half2_rn(f0.z, f0.w);
        __half2 h2 = __floats2half2_rn(f1.x, f1.y);
        __half2 h3 = __floats2half2_rn(f1.z, f1.w);
        uint4 o;
        o.x = *reinterpret_cast<uint32_t*>(&h0);
        o.y = *reinterpret_cast<uint32_t*>(&h1);
        o.z = *reinterpret_cast<uint32_t*>(&h2);
        o.w = *reinterpret_cast<uint32_t*>(&h3);
        *reinterpret_cast<uint4*>(&g_xh[i]) = o;
    } else {
        __shared__ float t[32][33];
        int bidx = blockIdx.x - NC_BLOCKS;
        int bx = bidx & 31;        // n tile
        int by = bidx >> 5;        // k tile
        int tx = threadIdx.x & 31;
        int ty = threadIdx.x >> 5; // 0..7
        int n = bx * 32 + tx;
        int k = by * 32 + ty;
#pragma unroll
        for (int i = 0; i < 4; ++i)
            t[ty + i * 8][tx] = W[(size_t)(k + i * 8) * N_DIM + n];
        __syncthreads();
        int n2 = bx * 32 + ty;
        int k2 = by * 32 + tx;
#pragma unroll
        for (int i = 0; i < 4; ++i)
            g_Wt[(size_t)(n2 + i * 8) * K_DIM + k2] =
                __float2half(t[tx][ty + i * 8]);
    }
}

// ============================ main fused kernel ============================
// 4 warps in 2x2 (warp tile 64x32, acc[4][4][4]=64 regs); 4 CTAs/SM (16 warps/SM,
// 4 independent warps per SMSP). 2-stage cp.async pipeline, 48KB smem/CTA.
// Chunk strides fold into immediates: one base reg per tensor per space.
__global__ __launch_bounds__(THREADS, 4)
void fused_gemm_gn_swish_kernel(const float* __restrict__ bias,
                                const float* __restrict__ mw,
                                float* __restrict__ out) {
    extern __shared__ char smem[];
    uint32_t sb = smem_u32(smem);
    const int tid  = threadIdx.x;
    const int lane = tid & 31;
    const int wid  = tid >> 5;
    const int wm   = wid >> 1;   // 0..1  (M warp row, 64 rows)
    const int wn   = wid & 1;    // 0..1  (N warp col, 32 cols = one GN group)
    const int m0   = blockIdx.y * BM;
    const int n0   = blockIdx.x * BN;

    uint32_t sA = sb;                      // 2 x 16KB
    uint32_t sB = sb + 2 * A_STAGE;        // 2 x 8KB

    // ---- load addressing: base offsets; chunk i adds immediates ----
    const int r0 = tid >> 3, c0 = tid & 7;
    const uint32_t s_off = (uint32_t)(r0 * 128 + (((c0 ^ (r0 & 7))) << 4));
    const uint32_t g_off = (uint32_t)(r0 * K_DIM + c0 * 8);
    // A: 8 chunks (rows r0+16i), B: 4 chunks; stride per chunk: smem +2048B,
    // global +16*K_DIM elements (r&7 invariant -> same swizzle).

    const __half* ag = g_xh + (size_t)m0 * K_DIM + g_off;
    const __half* bg = g_Wt + (size_t)n0 * K_DIM + g_off;

    // prologue: fill stage 0
#pragma unroll
    for (int i = 0; i < 8; ++i) cp_async16(sA + s_off + i * 2048, ag + i * 16 * K_DIM);
#pragma unroll
    for (int i = 0; i < 4; ++i) cp_async16(sB + s_off + i * 2048, bg + i * 16 * K_DIM);
    CP_COMMIT();
    ag += BK; bg += BK;

    float acc[4][4][4];
#pragma unroll
    for (int i = 0; i < 4; ++i)
#pragma unroll
        for (int j = 0; j < 4; ++j)
#pragma unroll
            for (int e = 0; e < 4; ++e) acc[i][j][e] = 0.0f;

    // ldmatrix lane addressing
    const int lrow   = lane & 15;
    const int lchunk = lane >> 4;
    const uint32_t aRow = (uint32_t)(wm * 64 + lrow) * 128;
    const uint32_t bRow = (uint32_t)(wn * 32 + lrow) * 128;
    uint32_t soff[4];
#pragma unroll
    for (int ks = 0; ks < 4; ++ks)
        soff[ks] = (uint32_t)(((ks * 2 + lchunk) ^ (lrow & 7)) << 4);

    for (int kt = 0; kt < KTILES; ++kt) {
        CP_WAIT(0);          // stage kt resident
        __syncthreads();     // all warps done with the other buffer; loads visible

        // issue stage kt+1 into the other buffer
        if (kt + 1 < KTILES) {
            uint32_t dA = sA + ((kt + 1) & 1) * A_STAGE;
            uint32_t dB = sB + ((kt + 1) & 1) * B_STAGE;
#pragma unroll
            for (int i = 0; i < 8; ++i) cp_async16(dA + s_off + i * 2048, ag + i * 16 * K_DIM);
#pragma unroll
            for (int i = 0; i < 4; ++i) cp_async16(dB + s_off + i * 2048, bg + i * 16 * K_DIM);
            CP_COMMIT();
            ag += BK; bg += BK;
        }

        uint32_t aB = sA + (kt & 1) * A_STAGE + aRow;
        uint32_t bB = sB + (kt & 1) * B_STAGE + bRow;
#pragma unroll
        for (int ks = 0; ks < 4; ++ks) {
            uint32_t a[4][4], b[2][4];
#pragma unroll
            for (int mi = 0; mi < 4; ++mi)
                ldsm_x4(a[mi][0], a[mi][1], a[mi][2], a[mi][3],
                        aB + mi * (16 * 128) + soff[ks]);
#pragma unroll
            for (int p = 0; p < 2; ++p)
                ldsm_x4(b[p][0], b[p][1], b[p][2], b[p][3],
                        bB + p * (16 * 128) + soff[ks]);
            // b[p][0]=n(lo8,p) k0-7, b[p][1]=n(hi8,p) k0-7, b[p][2]=lo k8-15, b[p][3]=hi k8-15
#pragma unroll
            for (int mi = 0; mi < 4; ++mi) {
#pragma unroll
                for (int ni = 0; ni < 4; ++ni) {
                    uint32_t b0 = (ni & 1) ? b[ni >> 1][1] : b[ni >> 1][0];
                    uint32_t b1 = (ni & 1) ? b[ni >> 1][3] : b[ni >> 1][2];
                    mma16816(acc[mi][ni], a[mi], b0, b1);
                }
            }
        }
    }

    // -------- fused epilogue: bias + GroupNorm(32ch) + swish * w * swish --------
    // Warp covers exactly one 32-channel group: quad shfl reduce (xor 1,2).
    const int q  = lane >> 2;
    const int qt = lane & 3;
    const float inv32 = 1.0f / 32.0f;
    const float* bp = bias + n0 + wn * 32 + qt * 2;
    const float* wp = mw   + n0 + wn * 32 + qt * 2;

#pragma unroll
    for (int mi = 0; mi < 4; ++mi) {
#pragma unroll
        for (int half = 0; half < 2; ++half) {
            int row = m0 + wm * 64 + mi * 16 + half * 8 + q;
            float* op = out + (size_t)row * N_DIM + n0 + wn * 32;

            float v[8];
            float sum = 0.0f, ssq = 0.0f;
#pragma unroll
            for (int ni = 0; ni < 4; ++ni) {
                float2 bv = *reinterpret_cast<const float2*>(bp + ni * 8);
#pragma unroll
                for (int e = 0; e < 2; ++e) {
                    float val = acc[mi][ni][half * 2 + e] + ((e == 0) ? bv.x : bv.y);
                    v[ni * 2 + e] = val;
                    sum += val;
                    ssq = fmaf(val, val, ssq);
                }
            }
            sum += __shfl_xor_sync(0xffffffffu, sum, 1);
            ssq += __shfl_xor_sync(0xffffffffu, ssq, 1);
            sum += __shfl_xor_sync(0xffffffffu, sum, 2);
            ssq += __shfl_xor_sync(0xffffffffu, ssq, 2);
            float mean = sum * inv32;
            float var  = fmaf(ssq, inv32, -mean * mean);
            float rstd = rsqrtf(var + 1e-5f);

#pragma unroll
            for (int ni = 0; ni < 4; ++ni) {
                float2 wv = *reinterpret_cast<const float2*>(wp + ni * 8);
                float2 o;
#pragma unroll
                for (int e = 0; e < 2; ++e) {
                    float nv = (v[ni * 2 + e] - mean) * rstd;
                    float s  = nv * fsig(nv);
                    float mm = s * ((e == 0) ? wv.x : wv.y);
                    float ov = mm * fsig(mm);
                    if (e == 0) o.x = ov; else o.y = ov;
                }
                __stcs(reinterpret_cast<float2*>(op + ni * 8 + qt * 2), o);
            }
        }
    }
}

// ============================ launch ============================
extern "C" void kernel_launch(void* const* d_in, const int* in_sizes, int n_in,
                              void* d_out, int out_size) {
    const float* x  = (const float*)d_in[0];
    const float* W  = (const float*)d_in[1];
    const float* b  = (const float*)d_in[2];
    const float* mw = (const float*)d_in[3];
    float* out = (float*)d_out;

    const size_t M = (size_t)in_sizes[0] / K_DIM;   // 65536

    // 1) merged pre-pass: x -> fp16 and W -> Wt fp16
    prepass_kernel<<<NC_BLOCKS + (N_DIM / 32) * (K_DIM / 32), 256>>>(x, W);

    // 2) fused GEMM + bias + GroupNorm + Swish chain (4 CTAs/SM)
    cudaFuncSetAttribute(fused_gemm_gn_swish_kernel,
                         cudaFuncAttributeMaxDynamicSharedMemorySize, SMEM_TOTAL);
    dim3 grid(N_DIM / BN, (unsigned)(M / BM));  // x fastest: 16 N-tiles share an A band in L2
    fused_gemm_gn_swish_kernel<<<grid, THREADS, SMEM_TOTAL>>>(b, mw, out);
}